// round 7
// baseline (speedup 1.0000x reference)
#include <cuda_runtime.h>
#include <cfloat>

#define BB 4
#define NN 4096
#define SS 1024
#define C1v 128
#define C2v 256
#define COv 128
#define KNNK 16
#define FEAT 384
#define MM (BB*NN)        // 16384 total points

// ---------------- scratch (device globals; no allocation allowed) -------------
static __device__ float g_p2t[BB*SS*C2v];     // points2 transposed [B][S][C2]
static __device__ float g_feat[MM*FEAT];      // concat features   [M][384]
static __device__ float g_xpre[BB*COv*NN];    // fuse conv out (pre-BN)
static __device__ float g_x[BB*COv*NN];       // x = relu(bn(.))   [B][CO][N]
static __device__ float g_xt[MM*COv];         // x transposed      [M][CO]
static __device__ float g_dx[MM*COv];         // laplacian input   [M][CO]
static __device__ float g_hr[BB*COv*NN];      // relu(lu conv)     [B][CO][N]
static __device__ int   g_knn[MM*KNNK];
static __device__ float g_w3[MM*3];
static __device__ int   g_i3[MM*3];
static __device__ float g_stats[4*COv];       // [sum1|sq1|sum2|sq2]
static __device__ float g_ab[4*COv];          // [a1|b1|a2|b2]

// ---------------- zero stats --------------------------------------------------
__global__ void k_zero() {
    int t = threadIdx.x;
    if (t < 4*COv) g_stats[t] = 0.f;
}

// ---------------- generic 32x32 tiled transpose -------------------------------
// in [b][R][Cn] -> out [b][Cn][ostride] (write col offset 0, row stride ostride)
__global__ void k_transpose(const float* __restrict__ in, float* __restrict__ out,
                            int R, int Cn, int ostride) {
    __shared__ float tile[32][33];
    int b = blockIdx.z;
    int x0 = blockIdx.x*32, y0 = blockIdx.y*32;
    int tx = threadIdx.x, ty = threadIdx.y;
    const float* ip = in + (size_t)b*R*Cn;
    float* op = out + (size_t)b*Cn*ostride;
#pragma unroll
    for (int q = 0; q < 4; q++)
        tile[ty+q*8][tx] = ip[(size_t)(y0+ty+q*8)*Cn + x0+tx];
    __syncthreads();
#pragma unroll
    for (int q = 0; q < 4; q++)
        op[(size_t)(x0+ty+q*8)*ostride + y0+tx] = tile[tx][ty+q*8];
}

// ---------------- top-3 FARTHEST (faithful torch topk bug) --------------------
// block: 256 thr = 128 rows x 2 cols; each col scans 512 of the 1024 candidates
__global__ __launch_bounds__(256) void k_top3(const float* __restrict__ xyz1,
                                              const float* __restrict__ xyz2) {
    __shared__ float4 c2[SS];           // 16 KB
    __shared__ float md[128*6];
    __shared__ int   mi[128*6];
    int t = threadIdx.x, b = blockIdx.y;
    for (int i = t; i < SS; i += 256) {
        const float* p = xyz2 + (size_t)(b*SS + i)*3;
        float x = p[0], y = p[1], z = p[2];
        c2[i] = make_float4(x, y, z, fmaf(z, z, fmaf(y, y, x*x)));
    }
    __syncthreads();
    int row = t & 127, col = t >> 7;
    int n = blockIdx.x*128 + row;
    const float* q = xyz1 + (size_t)(b*NN + n)*3;
    float qx = q[0], qy = q[1], qz = q[2];
    float sn = fmaf(qz, qz, fmaf(qy, qy, qx*qx));
    float d0 = -FLT_MAX, d1 = -FLT_MAX, d2 = -FLT_MAX;
    int i0 = 0, i1 = 0, i2 = 0;
    int j0 = col*512;
    for (int jj = 0; jj < 512; jj++) {
        float4 f = c2[j0+jj];
        float dot = fmaf(qz, f.z, fmaf(qy, f.y, qx*f.x));
        float d = fmaf(-2.f, dot, sn + f.w);
        if (d > d2) {
            if (d > d1) {
                d2 = d1; i2 = i1;
                if (d > d0) { d1 = d0; i1 = i0; d0 = d; i0 = j0+jj; }
                else        { d1 = d;  i1 = j0+jj; }
            } else { d2 = d; i2 = j0+jj; }
        }
    }
    int base = row*6 + col*3;
    md[base] = d0; md[base+1] = d1; md[base+2] = d2;
    mi[base] = i0; mi[base+1] = i1; mi[base+2] = i2;
    __syncthreads();
    if (col == 0) {
        float e0 = -FLT_MAX, e1 = -FLT_MAX, e2 = -FLT_MAX;
        int a0 = 0, a1 = 0, a2 = 0;
#pragma unroll
        for (int e = 0; e < 6; e++) {
            float d = md[row*6+e]; int ii = mi[row*6+e];
            if (d > e2) {
                if (d > e1) {
                    e2 = e1; a2 = a1;
                    if (d > e0) { e1 = e0; a1 = a0; e0 = d; a0 = ii; }
                    else        { e1 = d;  a1 = ii; }
                } else { e2 = d; a2 = ii; }
            }
        }
        float r0 = 1.f/(e0 + 1e-8f), r1 = 1.f/(e1 + 1e-8f), r2 = 1.f/(e2 + 1e-8f);
        float ws = r0 + r1 + r2;
        int m = b*NN + n;
        g_w3[m*3]   = r0/ws; g_w3[m*3+1] = r1/ws; g_w3[m*3+2] = r2/ws;
        g_i3[m*3]   = a0;    g_i3[m*3+1] = a1;    g_i3[m*3+2] = a2;
    }
}

// ---------------- interp -> feat[...,128:384] ---------------------------------
__global__ void k_interp() {
    int idx = blockIdx.x*256 + threadIdx.x;     // M*C2 threads
    int m = idx >> 8, c = idx & 255;
    int b = m >> 12;
    const int*   ii = g_i3 + m*3;
    const float* ww = g_w3 + m*3;
    const float* base = g_p2t + (size_t)b*SS*C2v + c;
    float v =            ww[0]*base[(size_t)ii[0]*C2v];
    v = fmaf(ww[1], base[(size_t)ii[1]*C2v], v);
    v = fmaf(ww[2], base[(size_t)ii[2]*C2v], v);
    g_feat[(size_t)m*FEAT + C1v + c] = v;
}

// ---------------- tiled SIMT GEMM with fused bias/relu/stats ------------------
// C[m][o] = sum_k A[m][k]*W[o][k] + bias[o]; out layout [B][CO][N]
template<int KT, bool RELU>
__global__ __launch_bounds__(256) void k_gemm(const float* __restrict__ A,
                                              const float* __restrict__ W,
                                              const float* __restrict__ bias,
                                              float* __restrict__ outp,
                                              float* __restrict__ stats) {
    constexpr int BM = 64, BO = 64, BK = 16;
    __shared__ __align__(16) float As[BK][BM+4];
    __shared__ __align__(16) float Ws[BK][BO+4];
    __shared__ float ssum[BO], ssq[BO];
    int t = threadIdx.x;
    int m0 = blockIdx.x*BM, o0 = blockIdx.y*BO;
    if (t < BO) { ssum[t] = 0.f; ssq[t] = 0.f; }
    int trow = t >> 4, tcol = t & 15;
    float acc[4][4] = {};
    for (int k0 = 0; k0 < KT; k0 += BK) {
        __syncthreads();
#pragma unroll
        for (int qd = 0; qd < 4; qd++) {
            int l = t + qd*256;
            int kk = l & 15, mm = l >> 4;
            As[kk][mm] = A[(size_t)(m0+mm)*KT + k0+kk];
            Ws[kk][mm] = W[(size_t)(o0+mm)*KT + k0+kk];
        }
        __syncthreads();
#pragma unroll
        for (int k = 0; k < BK; k++) {
            float4 av = *(const float4*)&As[k][trow*4];
            float4 wv = *(const float4*)&Ws[k][tcol*4];
            float a[4] = {av.x, av.y, av.z, av.w};
            float w[4] = {wv.x, wv.y, wv.z, wv.w};
#pragma unroll
            for (int i = 0; i < 4; i++)
#pragma unroll
                for (int j = 0; j < 4; j++)
                    acc[i][j] = fmaf(a[i], w[j], acc[i][j]);
        }
    }
    __syncthreads();
    int n_base = (m0 & (NN-1)) + trow*4;
    int b = m0 >> 12;
#pragma unroll
    for (int j = 0; j < 4; j++) {
        int o = o0 + tcol*4 + j;
        float bv = bias[o];
        float4 v4;
        float s = 0.f, qsum = 0.f;
        float vs[4];
#pragma unroll
        for (int i = 0; i < 4; i++) {
            float v = acc[i][j] + bv;
            if (RELU) v = fmaxf(v, 0.f);
            vs[i] = v;
            s += v;
            qsum = fmaf(v, v, qsum);
        }
        v4.x = vs[0]; v4.y = vs[1]; v4.z = vs[2]; v4.w = vs[3];
        *(float4*)(outp + ((size_t)(b*COv + o)*NN) + n_base) = v4;
        atomicAdd(&ssum[tcol*4+j], s);
        atomicAdd(&ssq[tcol*4+j], qsum);
    }
    __syncthreads();
    if (t < BO) {
        atomicAdd(&stats[o0 + t],       ssum[t]);
        atomicAdd(&stats[COv + o0 + t], ssq[t]);
    }
}

// ---------------- BN finalize: stats -> scale/shift ---------------------------
__global__ void k_finalize(const float* __restrict__ stats,
                           const float* __restrict__ gamma,
                           const float* __restrict__ beta,
                           float* __restrict__ ab) {
    int t = threadIdx.x;
    if (t < COv) {
        float invn = 1.f / (float)MM;
        float mean = stats[t] * invn;
        float var  = fmaf(-mean, mean, stats[COv + t] * invn);
        float a = gamma[t] * rsqrtf(var + 1e-5f);
        ab[t] = a;
        ab[COv + t] = beta[t] - mean*a;
    }
}

// ---------------- apply BN+ReLU to x, also write transposed copy --------------
__global__ void k_bnrelu_tr() {
    __shared__ float tile[32][33];
    int b = blockIdx.z;
    int c0 = blockIdx.y*32, n0 = blockIdx.x*32;
    int tx = threadIdx.x, ty = threadIdx.y;
    const float* A = g_xpre + (size_t)b*COv*NN;
    float* X = g_x + (size_t)b*COv*NN;
#pragma unroll
    for (int qd = 0; qd < 4; qd++) {
        int c = c0 + ty + qd*8;
        float v = fmaf(g_ab[c], A[(size_t)c*NN + n0+tx], g_ab[COv + c]);
        v = fmaxf(v, 0.f);
        X[(size_t)c*NN + n0+tx] = v;
        tile[ty+qd*8][tx] = v;
    }
    __syncthreads();
#pragma unroll
    for (int qd = 0; qd < 4; qd++) {
        int n = n0 + ty + qd*8;
        g_xt[((size_t)(b*NN) + n)*COv + c0 + tx] = tile[tx][ty+qd*8];
    }
}

// ---------------- self-KNN top-16 (smallest), 4 threads per row ---------------
__global__ __launch_bounds__(256) void k_knn(const float* __restrict__ xyz1) {
    union SH {
        float4 cand[2048];                           // 32 KB staging
        struct { float d[4096]; int i[4096]; } mg;   // 32 KB merge (reused)
    };
    __shared__ SH sh;
    int t = threadIdx.x, b = blockIdx.y;
    int row = t & 63, col = t >> 6;
    int n = blockIdx.x*64 + row;
    const float* q = xyz1 + (size_t)(b*NN + n)*3;
    float qx = q[0], qy = q[1], qz = q[2];
    float sn = fmaf(qz, qz, fmaf(qy, qy, qx*qx));
    float bd[16]; int bi[16];
#pragma unroll
    for (int r = 0; r < 16; r++) { bd[r] = FLT_MAX; bi[r] = 0; }
    float cm = FLT_MAX;
    for (int ch = 0; ch < 2; ch++) {
        __syncthreads();
        for (int i = t; i < 2048; i += 256) {
            const float* p = xyz1 + (size_t)(b*NN + ch*2048 + i)*3;
            float x = p[0], y = p[1], z = p[2];
            sh.cand[i] = make_float4(x, y, z, fmaf(z, z, fmaf(y, y, x*x)));
        }
        __syncthreads();
        int base = col*512;
        int gbase = ch*2048 + base;
        for (int jj = 0; jj < 512; jj++) {
            float4 f = sh.cand[base+jj];
            float dot = fmaf(qz, f.z, fmaf(qy, f.y, qx*f.x));
            float d = fmaf(-2.f, dot, sn + f.w);
            if (d < cm) {                 // strict: ties keep earlier index
                bool done = false;
#pragma unroll
                for (int r = 0; r < 16; r++)
                    if (!done && bd[r] == cm) { bd[r] = d; bi[r] = gbase+jj; done = true; }
                cm = bd[0];
#pragma unroll
                for (int r = 1; r < 16; r++) cm = fmaxf(cm, bd[r]);
            }
        }
    }
    __syncthreads();
#pragma unroll
    for (int r = 0; r < 16; r++) {
        sh.mg.d[row*64 + col*16 + r] = bd[r];
        sh.mg.i[row*64 + col*16 + r] = bi[r];
    }
    __syncthreads();
    if (col == 0) {
        float fd[16]; int fi[16];
#pragma unroll
        for (int r = 0; r < 16; r++) { fd[r] = FLT_MAX; fi[r] = 0; }
        float fm = FLT_MAX;
        for (int e = 0; e < 64; e++) {
            float d = sh.mg.d[row*64 + e];
            int  id = sh.mg.i[row*64 + e];
            if (d < fm) {
                bool done = false;
#pragma unroll
                for (int r = 0; r < 16; r++)
                    if (!done && fd[r] == fm) { fd[r] = d; fi[r] = id; done = true; }
                fm = fd[0];
#pragma unroll
                for (int r = 1; r < 16; r++) fm = fmaxf(fm, fd[r]);
            }
        }
        int* kp = g_knn + (size_t)(b*NN + n)*KNNK;
#pragma unroll
        for (int r = 0; r < 16; r++) kp[r] = fi[r];
    }
}

// ---------------- dx = sum of 16 NN feature rows minus self -------------------
__global__ void k_gather() {
    int idx = blockIdx.x*256 + threadIdx.x;     // M*32 threads (float4 per thread)
    int m = idx >> 5, c4 = idx & 31;
    int b = m >> 12;
    const int* kn = g_knn + (size_t)m*KNNK;
    const float4* xt = (const float4*)g_xt;
    float4 s = xt[(size_t)m*32 + c4];
    float ax = -s.x, ay = -s.y, az = -s.z, aw = -s.w;
#pragma unroll
    for (int j = 0; j < 16; j++) {
        int id = kn[j];
        float4 v = xt[((size_t)(b << 12) + id)*32 + c4];
        ax += v.x; ay += v.y; az += v.z; aw += v.w;
    }
    ((float4*)g_dx)[(size_t)m*32 + c4] = make_float4(ax, ay, az, aw);
}

// ---------------- out = x + bn2(hr) -------------------------------------------
__global__ void k_final(float* __restrict__ out) {
    int idx = blockIdx.x*256 + threadIdx.x;     // B*CO*N threads
    int c = (idx >> 12) & (COv-1);
    out[idx] = g_x[idx] + fmaf(g_ab[2*COv + c], g_hr[idx], g_ab[3*COv + c]);
}

// ---------------- launch ------------------------------------------------------
extern "C" void kernel_launch(void* const* d_in, const int* in_sizes, int n_in,
                              void* d_out, int out_size) {
    const float* xyz1    = (const float*)d_in[0];
    const float* xyz2    = (const float*)d_in[1];
    const float* points1 = (const float*)d_in[2];
    const float* points2 = (const float*)d_in[3];
    const float* fuse_w  = (const float*)d_in[4];
    const float* fuse_b  = (const float*)d_in[5];
    const float* fuse_g  = (const float*)d_in[6];
    const float* fuse_be = (const float*)d_in[7];
    const float* lu_w    = (const float*)d_in[8];
    const float* lu_b    = (const float*)d_in[9];
    const float* lu_g    = (const float*)d_in[10];
    const float* lu_be   = (const float*)d_in[11];
    float* out = (float*)d_out;

    float *p2t, *feat, *xpre, *stats, *ab, *hr, *xt_g, *dx_g;
    cudaGetSymbolAddress((void**)&p2t,  g_p2t);
    cudaGetSymbolAddress((void**)&feat, g_feat);
    cudaGetSymbolAddress((void**)&xpre, g_xpre);
    cudaGetSymbolAddress((void**)&stats,g_stats);
    cudaGetSymbolAddress((void**)&ab,   g_ab);
    cudaGetSymbolAddress((void**)&hr,   g_hr);
    cudaGetSymbolAddress((void**)&xt_g, g_xt);
    cudaGetSymbolAddress((void**)&dx_g, g_dx);

    k_zero<<<1, 512>>>();
    // points2 [B][256][1024] -> p2t [B][1024][256]
    k_transpose<<<dim3(SS/32, C2v/32, BB), dim3(32,8)>>>(points2, p2t, C2v, SS, C2v);
    // points1 [B][128][4096] -> feat[...,0:128] (row stride 384)
    k_transpose<<<dim3(NN/32, C1v/32, BB), dim3(32,8)>>>(points1, feat, C1v, NN, FEAT);
    k_top3<<<dim3(NN/128, BB), 256>>>(xyz1, xyz2);
    k_interp<<<(MM*C2v)/256, 256>>>();
    k_gemm<FEAT, false><<<dim3(MM/64, COv/64), 256>>>(feat, fuse_w, fuse_b, xpre, stats);
    k_finalize<<<1, 128>>>(stats, fuse_g, fuse_be, ab);
    k_bnrelu_tr<<<dim3(NN/32, COv/32, BB), dim3(32,8)>>>();
    k_knn<<<dim3(NN/64, BB), 256>>>(xyz1);
    k_gather<<<(MM*32)/256, 256>>>();
    k_gemm<COv, true><<<dim3(MM/64, COv/64), 256>>>(dx_g, lu_w, lu_b, hr, stats + 2*COv);
    k_finalize<<<1, 128>>>(stats + 2*COv, lu_g, lu_be, ab + 2*COv);
    k_final<<<(BB*COv*NN)/256, 256>>>(out);
    (void)in_sizes; (void)n_in; (void)out_size; (void)xt_g;
}